// round 1
// baseline (speedup 1.0000x reference)
#include <cuda_runtime.h>
#include <math.h>
#include <float.h>

#define BB    32
#define CC    384
#define HH    56
#define WW    56
#define NN    3136
#define TOPK  98
#define NTOK  99
#define NHEAD 8
#define HDIM  48
#define EPSB  1e-5f

// ---------------- device scratch (no allocations allowed) ----------------
__device__ float g_h1[(size_t)BB*CC*NN];     // gelu(fc1(bn(x)))
__device__ float g_h2[(size_t)BB*CC*NN];     // depthwise out
__device__ float g_scores[BB*NN];
__device__ float g_sumx [BB*CC];
__device__ float g_sumx2[BB*CC];
__device__ int   g_topidx[BB*TOPK];
__device__ float g_tokens [BB*NTOK*CC];
__device__ float g_qkv    [BB*NTOK*3*CC];
__device__ float g_attnout[BB*NTOK*CC];
__device__ float g_ptok   [BB*NTOK*CC];      // proj_w @ attn tokens
__device__ float g_W1[CC*CC];
__device__ float g_b1[CC];
__device__ float g_W2[CC*CC];                // proj_w @ fc2_w
__device__ float g_b2[CC];                   // proj_w @ fc2_b + proj_b
__device__ float g_bnA[CC];
__device__ float g_bnC[CC];

__device__ __forceinline__ float gelu_exact(float v){
    return 0.5f * v * (1.0f + erff(v * 0.70710678118654752440f));
}

// ---------------- per-(b,c) sums over n (for bg + BN stats) ----------------
__global__ void k_colstats(const float* __restrict__ x){
    int bc = blockIdx.x;
    const float* p = x + (size_t)bc * NN;
    float s = 0.f, s2 = 0.f;
    for (int n = threadIdx.x; n < NN; n += blockDim.x){
        float v = p[n]; s += v; s2 = fmaf(v, v, s2);
    }
    for (int o = 16; o; o >>= 1){
        s  += __shfl_down_sync(~0u, s , o);
        s2 += __shfl_down_sync(~0u, s2, o);
    }
    __shared__ float sh[8], sh2[8];
    int w = threadIdx.x >> 5, l = threadIdx.x & 31;
    if (l == 0){ sh[w] = s; sh2[w] = s2; }
    __syncthreads();
    if (threadIdx.x == 0){
        float t = 0.f, t2 = 0.f;
        int nw = blockDim.x >> 5;
        for (int i = 0; i < nw; i++){ t += sh[i]; t2 += sh2[i]; }
        g_sumx[bc] = t; g_sumx2[bc] = t2;
    }
}

// ---------------- salience scores: sum over c of x^2 ----------------
__global__ void k_scores(const float* __restrict__ x){
    int n = blockIdx.x * blockDim.x + threadIdx.x;
    int b = blockIdx.y;
    if (n >= NN) return;
    const float* p = x + (size_t)b * CC * NN + n;
    float s = 0.f;
    #pragma unroll 4
    for (int c = 0; c < CC; c++){
        float v = p[(size_t)c * NN];
        s = fmaf(v, v, s);
    }
    g_scores[b*NN + n] = s;
}

// ---------------- BN stats -> affine fold (a,c) ----------------
__global__ void k_bnstats(const float* __restrict__ bn_g, const float* __restrict__ bn_b){
    int c = threadIdx.x;
    float s = 0.f, s2 = 0.f;
    for (int b = 0; b < BB; b++){ s += g_sumx[b*CC + c]; s2 += g_sumx2[b*CC + c]; }
    float inv = 1.f / ((float)BB * (float)NN);
    float mu  = s * inv;
    float var = s2 * inv - mu * mu;
    float a   = bn_g[c] * rsqrtf(var + EPSB);
    g_bnA[c] = a;
    g_bnC[c] = bn_b[c] - mu * a;
}

// ---------------- fold BN into fc1: W1 = fc1_w * a_c ; b1 = fc1_w@c + fc1_b ----------------
__global__ void k_prepW1(const float* __restrict__ fc1_w, const float* __restrict__ fc1_b){
    int o = blockIdx.x, c = threadIdx.x;
    float w = fc1_w[o*CC + c];
    g_W1[o*CC + c] = w * g_bnA[c];
    __shared__ float red[CC];
    red[c] = w * g_bnC[c];
    __syncthreads();
    for (int s = 256; s > 0; s >>= 1){
        if (c < s && c + s < CC) red[c] += red[c + s];
        __syncthreads();
    }
    if (c == 0) g_b1[o] = fc1_b[o] + red[0];
}

// ---------------- fuse proj into fc2: W2 = proj_w @ fc2_w ; b2 = proj_w@fc2_b + proj_b ----------------
__global__ void k_prepW2(const float* __restrict__ proj_w, const float* __restrict__ fc2_w,
                         const float* __restrict__ fc2_b, const float* __restrict__ proj_b){
    int o = blockIdx.x, c = threadIdx.x;
    const float* pr = proj_w + o*CC;
    float acc = 0.f;
    for (int k = 0; k < CC; k++)
        acc = fmaf(pr[k], fc2_w[k*CC + c], acc);
    g_W2[o*CC + c] = acc;
    __shared__ float red[CC];
    red[c] = pr[c] * fc2_b[c];
    __syncthreads();
    for (int s = 256; s > 0; s >>= 1){
        if (c < s && c + s < CC) red[c] += red[c + s];
        __syncthreads();
    }
    if (c == 0) g_b2[o] = proj_b[o] + red[0];
}

// ---------------- top-K per batch (98 rounds of block argmax; output set-equivalent to jax top_k) ----
__global__ void k_topk(){
    int b = blockIdx.x;
    __shared__ float sv[NN];
    for (int n = threadIdx.x; n < NN; n += blockDim.x) sv[n] = g_scores[b*NN + n];
    __syncthreads();
    __shared__ float rv[32];
    __shared__ int   ri[32];
    int lane = threadIdx.x & 31, w = threadIdx.x >> 5;
    for (int it = 0; it < TOPK; ++it){
        float best = -FLT_MAX; int bi = NN;
        for (int n = threadIdx.x; n < NN; n += blockDim.x){
            float v = sv[n];
            if (v > best){ best = v; bi = n; }
        }
        for (int o = 16; o; o >>= 1){
            float ov = __shfl_down_sync(~0u, best, o);
            int   oi = __shfl_down_sync(~0u, bi , o);
            if (ov > best || (ov == best && oi < bi)){ best = ov; bi = oi; }
        }
        if (lane == 0){ rv[w] = best; ri[w] = bi; }
        __syncthreads();
        if (w == 0){
            best = rv[lane]; bi = ri[lane];  // blockDim == 1024 -> exactly 32 warps
            for (int o = 16; o; o >>= 1){
                float ov = __shfl_down_sync(~0u, best, o);
                int   oi = __shfl_down_sync(~0u, bi , o);
                if (ov > best || (ov == best && oi < bi)){ best = ov; bi = oi; }
            }
            if (lane == 0){
                g_topidx[b*TOPK + it] = bi;
                sv[bi] = -FLT_MAX;
            }
        }
        __syncthreads();
    }
}

// ---------------- gather tokens + background token ----------------
__global__ void k_tokens(const float* __restrict__ x){
    int b = blockIdx.x, c = threadIdx.x;
    const float* xb = x + ((size_t)b * CC + c) * NN;
    float acc = 0.f;
    for (int j = 0; j < TOPK; j++){
        int idx = g_topidx[b*TOPK + j];
        float v = xb[idx];
        g_tokens[((size_t)b*NTOK + j)*CC + c] = v;
        acc += v;
    }
    g_tokens[((size_t)b*NTOK + TOPK)*CC + c] =
        (g_sumx[b*CC + c] - acc) * (1.f / (float)(NN - TOPK));
}

// ---------------- generic small NT-GEMM: C[m,n] = sum_k A[m,k]*B[n,k] (+bias[n]) ----------------
__global__ void k_gemm_nt(const float* __restrict__ A, const float* __restrict__ Bm,
                          const float* __restrict__ bias, float* __restrict__ Cout,
                          int M, int No, int Kd){
    const int BM = 64, BN = 64, BK = 16;
    __shared__ float As[BK][BM];
    __shared__ float Bs[BK][BN];
    int tid = threadIdx.x;
    int n0 = blockIdx.x * BN, m0 = blockIdx.y * BM;
    int lm = tid >> 2, lk = (tid & 3) * 4;
    int tx = tid & 15, ty = tid >> 4;
    float acc[4][4] = {};
    for (int k0 = 0; k0 < Kd; k0 += BK){
        float4 av = make_float4(0.f,0.f,0.f,0.f);
        if (m0 + lm < M) av = *(const float4*)&A[(size_t)(m0 + lm)*Kd + k0 + lk];
        As[lk+0][lm] = av.x; As[lk+1][lm] = av.y; As[lk+2][lm] = av.z; As[lk+3][lm] = av.w;
        float4 bv = *(const float4*)&Bm[(size_t)(n0 + lm)*Kd + k0 + lk];
        Bs[lk+0][lm] = bv.x; Bs[lk+1][lm] = bv.y; Bs[lk+2][lm] = bv.z; Bs[lk+3][lm] = bv.w;
        __syncthreads();
        #pragma unroll
        for (int kk = 0; kk < BK; kk++){
            float a[4], b2[4];
            #pragma unroll
            for (int i = 0; i < 4; i++) a[i]  = As[kk][ty*4 + i];
            #pragma unroll
            for (int j = 0; j < 4; j++) b2[j] = Bs[kk][tx*4 + j];
            #pragma unroll
            for (int i = 0; i < 4; i++)
                #pragma unroll
                for (int j = 0; j < 4; j++)
                    acc[i][j] = fmaf(a[i], b2[j], acc[i][j]);
        }
        __syncthreads();
    }
    #pragma unroll
    for (int i = 0; i < 4; i++){
        int m = m0 + ty*4 + i;
        if (m >= M) continue;
        #pragma unroll
        for (int j = 0; j < 4; j++){
            int n = n0 + tx*4 + j;
            float v = acc[i][j];
            if (bias) v += bias[n];
            Cout[(size_t)m*No + n] = v;
        }
    }
}

// ---------------- attention over 99 tokens per (b, head) ----------------
__global__ void k_attention(){
    int b = blockIdx.x / NHEAD, h = blockIdx.x % NHEAD;
    __shared__ float Ks[NTOK][HDIM];
    __shared__ float Vs[NTOK][HDIM];
    __shared__ float Qs[4][HDIM];
    __shared__ float Ps[4][NTOK];
    int tid = threadIdx.x;
    const float* qkvb = g_qkv + (size_t)b * NTOK * 3 * CC;
    for (int i = tid; i < NTOK*HDIM; i += blockDim.x){
        int t = i / HDIM, d = i % HDIM;
        Ks[t][d] = qkvb[(size_t)t*3*CC +   CC + h*HDIM + d];
        Vs[t][d] = qkvb[(size_t)t*3*CC + 2*CC + h*HDIM + d];
    }
    __syncthreads();
    int w = tid >> 5, lane = tid & 31;
    const float scale = rsqrtf((float)HDIM);
    for (int t = w; t < NTOK; t += 4){
        const float* qp = qkvb + (size_t)t*3*CC + h*HDIM;
        Qs[w][lane] = qp[lane];
        if (lane < HDIM - 32) Qs[w][lane + 32] = qp[lane + 32];
        __syncwarp();
        float sc[4]; float mx = -FLT_MAX;
        #pragma unroll
        for (int r = 0; r < 4; r++){
            int m = lane + r*32;
            float s = -FLT_MAX;
            if (m < NTOK){
                s = 0.f;
                #pragma unroll
                for (int d = 0; d < HDIM; d++) s = fmaf(Qs[w][d], Ks[m][d], s);
                s *= scale;
            }
            sc[r] = s; mx = fmaxf(mx, s);
        }
        for (int o = 16; o; o >>= 1) mx = fmaxf(mx, __shfl_xor_sync(~0u, mx, o));
        float sum = 0.f;
        #pragma unroll
        for (int r = 0; r < 4; r++){
            int m = lane + r*32;
            float e = (m < NTOK) ? expf(sc[r] - mx) : 0.f;
            sc[r] = e; sum += e;
        }
        for (int o = 16; o; o >>= 1) sum += __shfl_xor_sync(~0u, sum, o);
        float inv = 1.f / sum;
        #pragma unroll
        for (int r = 0; r < 4; r++){
            int m = lane + r*32;
            if (m < NTOK) Ps[w][m] = sc[r] * inv;
        }
        __syncwarp();
        for (int d = lane; d < HDIM; d += 32){
            float o = 0.f;
            for (int m = 0; m < NTOK; m++) o = fmaf(Ps[w][m], Vs[m][d], o);
            g_attnout[((size_t)b*NTOK + t)*CC + h*HDIM + d] = o;
        }
        __syncwarp();
    }
}

// ---------------- big NN-GEMM (per-batch): C[m,n] = sum_k A[m,k]*Bx[b,k,n] ----------------
// MODE 0: gelu(acc + bias[m])                -> h1
// MODE 1: acc + bias[m] + ptok_bg[b][m]      -> out
template<int MODE>
__global__ void k_gemm_nn(const float* __restrict__ A, const float* __restrict__ Bx,
                          float* __restrict__ Cy, const float* __restrict__ bias){
    int bb = blockIdx.z;
    const float* Bp = Bx + (size_t)bb * CC * NN;
    float*       Cp = Cy + (size_t)bb * CC * NN;
    int n0 = blockIdx.x * 128, m0 = blockIdx.y * 128;
    __shared__ float As[8][128];
    __shared__ float Bs[8][128];
    int tid = threadIdx.x;
    int am = tid >> 1, ak = (tid & 1) * 4;
    int bk = tid >> 5, bn = (tid & 31) * 4;
    int tx = tid & 15, ty = tid >> 4;
    float acc[8][8] = {};
    for (int k0 = 0; k0 < CC; k0 += 8){
        float4 av = *(const float4*)&A[(size_t)(m0 + am)*CC + k0 + ak];
        As[ak+0][am] = av.x; As[ak+1][am] = av.y; As[ak+2][am] = av.z; As[ak+3][am] = av.w;
        float4 bv = make_float4(0.f,0.f,0.f,0.f);
        if (n0 + bn < NN) bv = *(const float4*)&Bp[(size_t)(k0 + bk)*NN + n0 + bn];
        *(float4*)&Bs[bk][bn] = bv;
        __syncthreads();
        #pragma unroll
        for (int kk = 0; kk < 8; kk++){
            float a[8], b2[8];
            *(float4*)&a [0] = *(const float4*)&As[kk][ty*8];
            *(float4*)&a [4] = *(const float4*)&As[kk][ty*8 + 4];
            *(float4*)&b2[0] = *(const float4*)&Bs[kk][tx*8];
            *(float4*)&b2[4] = *(const float4*)&Bs[kk][tx*8 + 4];
            #pragma unroll
            for (int i = 0; i < 8; i++)
                #pragma unroll
                for (int j = 0; j < 8; j++)
                    acc[i][j] = fmaf(a[i], b2[j], acc[i][j]);
        }
        __syncthreads();
    }
    #pragma unroll
    for (int i = 0; i < 8; i++){
        int m = m0 + ty*8 + i;
        float bs = bias[m];
        if (MODE == 1) bs += g_ptok[((size_t)bb*NTOK + TOPK)*CC + m];
        #pragma unroll
        for (int jj = 0; jj < 8; jj += 4){
            int n = n0 + tx*8 + jj;
            if (n < NN){
                float t0 = acc[i][jj+0] + bs;
                float t1 = acc[i][jj+1] + bs;
                float t2 = acc[i][jj+2] + bs;
                float t3 = acc[i][jj+3] + bs;
                if (MODE == 0){
                    t0 = gelu_exact(t0); t1 = gelu_exact(t1);
                    t2 = gelu_exact(t2); t3 = gelu_exact(t3);
                }
                *(float4*)&Cp[(size_t)m*NN + n] = make_float4(t0, t1, t2, t3);
            }
        }
    }
}

// ---------------- depthwise 3x3 (SAME) ----------------
__global__ void k_dwconv(const float* __restrict__ dw_w, const float* __restrict__ dw_b){
    int n = blockIdx.x * blockDim.x + threadIdx.x;
    if (n >= NN) return;
    int bc = blockIdx.y;
    int c  = bc % CC;
    const float* src = g_h1 + (size_t)bc * NN;
    float*       dst = g_h2 + (size_t)bc * NN;
    int y = n / WW, xp = n % WW;
    const float* w = dw_w + c * 9;
    float acc = dw_b[c];
    #pragma unroll
    for (int dy = -1; dy <= 1; dy++){
        int yy = y + dy;
        if (yy < 0 || yy >= HH) continue;
        #pragma unroll
        for (int dx = -1; dx <= 1; dx++){
            int xw = xp + dx;
            if (xw < 0 || xw >= WW) continue;
            acc = fmaf(src[yy*WW + xw], w[(dy+1)*3 + (dx+1)], acc);
        }
    }
    dst[n] = acc;
}

// ---------------- scatter projected top tokens over the bg baseline ----------------
__global__ void k_scatter(float* __restrict__ out){
    int b = blockIdx.x / TOPK, j = blockIdx.x % TOPK;
    int o = threadIdx.x;
    int n = g_topidx[b*TOPK + j];
    float d = g_ptok[((size_t)b*NTOK + j   )*CC + o]
            - g_ptok[((size_t)b*NTOK + TOPK)*CC + o];
    out[((size_t)b*CC + o)*NN + n] += d;
}

// ---------------- host launch ----------------
extern "C" void kernel_launch(void* const* d_in, const int* in_sizes, int n_in,
                              void* d_out, int out_size){
    const float* x      = (const float*)d_in[0];
    const float* qkv_w  = (const float*)d_in[1];
    const float* qkv_b  = (const float*)d_in[2];
    const float* proj_w = (const float*)d_in[3];
    const float* proj_b = (const float*)d_in[4];
    const float* bn_g   = (const float*)d_in[5];
    const float* bn_b   = (const float*)d_in[6];
    const float* fc1_w  = (const float*)d_in[7];
    const float* fc1_b  = (const float*)d_in[8];
    const float* fc2_w  = (const float*)d_in[9];
    const float* fc2_b  = (const float*)d_in[10];
    const float* dw_w   = (const float*)d_in[11];
    const float* dw_b   = (const float*)d_in[12];
    float* out = (float*)d_out;

    float *p_tokens, *p_qkv, *p_attnout, *p_ptok, *p_W1, *p_b1, *p_W2, *p_b2, *p_h2;
    cudaGetSymbolAddress((void**)&p_tokens , g_tokens);
    cudaGetSymbolAddress((void**)&p_qkv    , g_qkv);
    cudaGetSymbolAddress((void**)&p_attnout, g_attnout);
    cudaGetSymbolAddress((void**)&p_ptok   , g_ptok);
    cudaGetSymbolAddress((void**)&p_W1     , g_W1);
    cudaGetSymbolAddress((void**)&p_b1     , g_b1);
    cudaGetSymbolAddress((void**)&p_W2     , g_W2);
    cudaGetSymbolAddress((void**)&p_b2     , g_b2);
    cudaGetSymbolAddress((void**)&p_h2     , g_h2);
    float* p_h1; cudaGetSymbolAddress((void**)&p_h1, g_h1);

    // reductions + stats
    k_colstats<<<BB*CC, 128>>>(x);
    k_scores  <<<dim3((NN + 255)/256, BB), 256>>>(x);
    k_bnstats <<<1, CC>>>(bn_g, bn_b);
    k_prepW1  <<<CC, CC>>>(fc1_w, fc1_b);
    k_prepW2  <<<CC, CC>>>(proj_w, fc2_w, fc2_b, proj_b);

    // salience branch (tiny)
    k_topk    <<<BB, 1024>>>();
    k_tokens  <<<BB, CC>>>(x);
    k_gemm_nt <<<dim3((3*CC)/64, (BB*NTOK + 63)/64), 256>>>(p_tokens, qkv_w, qkv_b, p_qkv,
                                                            BB*NTOK, 3*CC, CC);
    k_attention<<<BB*NHEAD, 128>>>();
    k_gemm_nt <<<dim3(CC/64, (BB*NTOK + 63)/64), 256>>>(p_attnout, proj_w, (const float*)nullptr,
                                                        p_ptok, BB*NTOK, CC, CC);

    // conv-mixer branch (heavy): BN folded into fc1, proj folded into fc2
    k_gemm_nn<0><<<dim3((NN + 127)/128, CC/128, BB), 256>>>(p_W1, x, p_h1, p_b1);
    k_dwconv    <<<dim3((NN + 255)/256, BB*CC), 256>>>(dw_w, dw_b);
    k_gemm_nn<1><<<dim3((NN + 127)/128, CC/128, BB), 256>>>(p_W2, p_h2, out, p_b2);

    // rank-99 correction at top-token positions
    k_scatter   <<<BB*TOPK, CC>>>(out);
}

// round 3
// speedup vs baseline: 1.4898x; 1.4898x over previous
#include <cuda_runtime.h>
#include <cuda_bf16.h>
#include <math.h>
#include <float.h>
#include <stdint.h>

#define BB    32
#define CC    384
#define HH    56
#define WW    56
#define NN    3136
#define TOPK  98
#define NTOK  99
#define NHEAD 8
#define HDIM  48
#define EPSB  1e-5f
#define MTOK  (BB*NTOK)   // 3168 tokens

// ===================== PTX helpers (sm_80-era, legal at compute_103) =====================
__device__ __forceinline__ uint32_t smem_to_u32(const void* smem_ptr) {
    uint32_t addr;
    asm("{ .reg .u64 tmp; cvta.to.shared.u64 tmp, %1; cvt.u32.u64 %0, tmp; }"
        : "=r"(addr) : "l"(smem_ptr));
    return addr;
}
#define CP_ASYNC16(dst, src, sz) \
    asm volatile("cp.async.cg.shared.global [%0], [%1], 16, %2;" \
        :: "r"((uint32_t)(dst)), "l"(src), "r"((uint32_t)(sz)) : "memory")
#define CP_ASYNC_COMMIT() asm volatile("cp.async.commit_group;" ::: "memory")
#define CP_ASYNC_WAIT1()  asm volatile("cp.async.wait_group 1;" ::: "memory")

__device__ __forceinline__ void ldsm_x4(uint32_t (&r)[4], uint32_t addr){
    asm volatile("ldmatrix.sync.aligned.m8n8.x4.shared.b16 {%0,%1,%2,%3}, [%4];"
        : "=r"(r[0]),"=r"(r[1]),"=r"(r[2]),"=r"(r[3]) : "r"(addr));
}
__device__ __forceinline__ void ldsm_x2(uint32_t (&r)[2], uint32_t addr){
    asm volatile("ldmatrix.sync.aligned.m8n8.x2.shared.b16 {%0,%1}, [%2];"
        : "=r"(r[0]),"=r"(r[1]) : "r"(addr));
}
__device__ __forceinline__ void mma16816(float (&d)[4], const uint32_t (&a)[4], const uint32_t (&b)[2]){
    asm volatile("mma.sync.aligned.m16n8k16.row.col.f32.bf16.bf16.f32 "
        "{%0,%1,%2,%3}, {%4,%5,%6,%7}, {%8,%9}, {%0,%1,%2,%3};"
        : "+f"(d[0]),"+f"(d[1]),"+f"(d[2]),"+f"(d[3])
        : "r"(a[0]),"r"(a[1]),"r"(a[2]),"r"(a[3]), "r"(b[0]),"r"(b[1]));
}

// ===================== device scratch =====================
__device__ float g_h1[(size_t)BB*CC*NN];            // gelu(fc1(bn(x)))  [b][c][n] fp32
__device__ __nv_bfloat16 g_xth[(size_t)BB*NN*CC];   // [b][n][c] bf16 hi (x, then dwconv out)
__device__ __nv_bfloat16 g_xtl[(size_t)BB*NN*CC];   // [b][n][c] bf16 lo
__device__ float g_scores[BB*NN];
__device__ float g_sumx [BB*CC];
__device__ float g_sumx2[BB*CC];
__device__ int   g_topidx[BB*TOPK];
__device__ float g_tokens [MTOK*CC];
__device__ float g_qkv    [(size_t)MTOK*3*CC];
__device__ float g_attnout[MTOK*CC];
__device__ float g_ptok   [MTOK*CC];
__device__ __nv_bfloat16 g_W1h[CC*CC], g_W1l[CC*CC];
__device__ __nv_bfloat16 g_W2h[CC*CC], g_W2l[CC*CC];
__device__ __nv_bfloat16 g_tokh[MTOK*CC], g_tokl[MTOK*CC];
__device__ __nv_bfloat16 g_aoh [MTOK*CC], g_aol [MTOK*CC];
__device__ __nv_bfloat16 g_qwh [3*CC*CC], g_qwl [3*CC*CC];
__device__ __nv_bfloat16 g_pwh [CC*CC],   g_pwl [CC*CC];
__device__ float g_b1[CC];
__device__ float g_b2[CC];
__device__ float g_bnA[CC];
__device__ float g_bnC[CC];

__device__ __forceinline__ float gelu_exact(float v){
    return 0.5f * v * (1.0f + erff(v * 0.70710678118654752440f));
}
__device__ __forceinline__ void split_bf16(float v, __nv_bfloat16& h, __nv_bfloat16& l){
    h = __float2bfloat16(v);
    l = __float2bfloat16(v - __bfloat162float(h));
}

// ===================== small prep kernels =====================
__global__ void k_colstats(const float* __restrict__ x){
    int bc = blockIdx.x;
    const float* p = x + (size_t)bc * NN;
    float s = 0.f, s2 = 0.f;
    for (int n = threadIdx.x; n < NN; n += blockDim.x){
        float v = p[n]; s += v; s2 = fmaf(v, v, s2);
    }
    for (int o = 16; o; o >>= 1){
        s  += __shfl_down_sync(~0u, s , o);
        s2 += __shfl_down_sync(~0u, s2, o);
    }
    __shared__ float sh[8], sh2[8];
    int w = threadIdx.x >> 5, l = threadIdx.x & 31;
    if (l == 0){ sh[w] = s; sh2[w] = s2; }
    __syncthreads();
    if (threadIdx.x == 0){
        float t = 0.f, t2 = 0.f;
        int nw = blockDim.x >> 5;
        for (int i = 0; i < nw; i++){ t += sh[i]; t2 += sh2[i]; }
        g_sumx[bc] = t; g_sumx2[bc] = t2;
    }
}

__global__ void k_scores(const float* __restrict__ x){
    int n = blockIdx.x * blockDim.x + threadIdx.x;
    int b = blockIdx.y;
    if (n >= NN) return;
    const float* p = x + (size_t)b * CC * NN + n;
    float s = 0.f;
    #pragma unroll 4
    for (int c = 0; c < CC; c++){
        float v = p[(size_t)c * NN];
        s = fmaf(v, v, s);
    }
    g_scores[b*NN + n] = s;
}

__global__ void k_bnstats(const float* __restrict__ bn_g, const float* __restrict__ bn_b){
    int c = threadIdx.x;
    float s = 0.f, s2 = 0.f;
    for (int b = 0; b < BB; b++){ s += g_sumx[b*CC + c]; s2 += g_sumx2[b*CC + c]; }
    float inv = 1.f / ((float)BB * (float)NN);
    float mu  = s * inv;
    float var = s2 * inv - mu * mu;
    float a   = bn_g[c] * rsqrtf(var + EPSB);
    g_bnA[c] = a;
    g_bnC[c] = bn_b[c] - mu * a;
}

__global__ void k_prepW1(const float* __restrict__ fc1_w, const float* __restrict__ fc1_b){
    int o = blockIdx.x, c = threadIdx.x;
    float w = fc1_w[o*CC + c];
    float w1 = w * g_bnA[c];
    __nv_bfloat16 h, l; split_bf16(w1, h, l);
    g_W1h[o*CC + c] = h; g_W1l[o*CC + c] = l;
    __shared__ float red[CC];
    red[c] = w * g_bnC[c];
    __syncthreads();
    for (int s = 256; s > 0; s >>= 1){
        if (c < s && c + s < CC) red[c] += red[c + s];
        __syncthreads();
    }
    if (c == 0) g_b1[o] = fc1_b[o] + red[0];
}

__global__ void k_prepW2(const float* __restrict__ proj_w, const float* __restrict__ fc2_w,
                         const float* __restrict__ fc2_b, const float* __restrict__ proj_b){
    int o = blockIdx.x, c = threadIdx.x;
    const float* pr = proj_w + o*CC;
    float acc = 0.f;
    for (int k = 0; k < CC; k++)
        acc = fmaf(pr[k], fc2_w[k*CC + c], acc);
    __nv_bfloat16 h, l; split_bf16(acc, h, l);
    g_W2h[o*CC + c] = h; g_W2l[o*CC + c] = l;
    __shared__ float red[CC];
    red[c] = pr[c] * fc2_b[c];
    __syncthreads();
    for (int s = 256; s > 0; s >>= 1){
        if (c < s && c + s < CC) red[c] += red[c + s];
        __syncthreads();
    }
    if (c == 0) g_b2[o] = proj_b[o] + red[0];
}

__global__ void k_split_rows(const float* __restrict__ src, __nv_bfloat16* __restrict__ dh,
                             __nv_bfloat16* __restrict__ dl, int n){
    int i = blockIdx.x * 256 + threadIdx.x;
    if (i < n){
        __nv_bfloat16 h, l; split_bf16(src[i], h, l);
        dh[i] = h; dl[i] = l;
    }
}

// ===================== topk + tokens =====================
__global__ void k_topk(){
    int b = blockIdx.x;
    __shared__ float sv[NN];
    for (int n = threadIdx.x; n < NN; n += blockDim.x) sv[n] = g_scores[b*NN + n];
    __syncthreads();
    __shared__ float rv[32];
    __shared__ int   ri[32];
    int lane = threadIdx.x & 31, w = threadIdx.x >> 5;
    for (int it = 0; it < TOPK; ++it){
        float best = -FLT_MAX; int bi = NN;
        for (int n = threadIdx.x; n < NN; n += blockDim.x){
            float v = sv[n];
            if (v > best){ best = v; bi = n; }
        }
        for (int o = 16; o; o >>= 1){
            float ov = __shfl_down_sync(~0u, best, o);
            int   oi = __shfl_down_sync(~0u, bi , o);
            if (ov > best || (ov == best && oi < bi)){ best = ov; bi = oi; }
        }
        if (lane == 0){ rv[w] = best; ri[w] = bi; }
        __syncthreads();
        if (w == 0){
            best = rv[lane]; bi = ri[lane];
            for (int o = 16; o; o >>= 1){
                float ov = __shfl_down_sync(~0u, best, o);
                int   oi = __shfl_down_sync(~0u, bi , o);
                if (ov > best || (ov == best && oi < bi)){ best = ov; bi = oi; }
            }
            if (lane == 0){
                g_topidx[b*TOPK + it] = bi;
                sv[bi] = -FLT_MAX;
            }
        }
        __syncthreads();
    }
}

__global__ void k_tokens(const float* __restrict__ x){
    int b = blockIdx.x, c = threadIdx.x;
    const float* xb = x + ((size_t)b * CC + c) * NN;
    float acc = 0.f;
    for (int j = 0; j < TOPK; j++){
        int idx = g_topidx[b*TOPK + j];
        float v = xb[idx];
        g_tokens[((size_t)b*NTOK + j)*CC + c] = v;
        acc += v;
    }
    g_tokens[((size_t)b*NTOK + TOPK)*CC + c] =
        (g_sumx[b*CC + c] - acc) * (1.f / (float)(NN - TOPK));
}

// ===================== attention over 99 tokens =====================
__global__ void k_attention(){
    int b = blockIdx.x / NHEAD, h = blockIdx.x % NHEAD;
    __shared__ float Ks[NTOK][HDIM];
    __shared__ float Vs[NTOK][HDIM];
    __shared__ float Qs[4][HDIM];
    __shared__ float Ps[4][NTOK];
    int tid = threadIdx.x;
    const float* qkvb = g_qkv + (size_t)b * NTOK * 3 * CC;
    for (int i = tid; i < NTOK*HDIM; i += blockDim.x){
        int t = i / HDIM, d = i % HDIM;
        Ks[t][d] = qkvb[(size_t)t*3*CC +   CC + h*HDIM + d];
        Vs[t][d] = qkvb[(size_t)t*3*CC + 2*CC + h*HDIM + d];
    }
    __syncthreads();
    int w = tid >> 5, lane = tid & 31;
    const float scale = rsqrtf((float)HDIM);
    for (int t = w; t < NTOK; t += 4){
        const float* qp = qkvb + (size_t)t*3*CC + h*HDIM;
        Qs[w][lane] = qp[lane];
        if (lane < HDIM - 32) Qs[w][lane + 32] = qp[lane + 32];
        __syncwarp();
        float sc[4]; float mx = -FLT_MAX;
        #pragma unroll
        for (int r = 0; r < 4; r++){
            int m = lane + r*32;
            float s = -FLT_MAX;
            if (m < NTOK){
                s = 0.f;
                #pragma unroll
                for (int d = 0; d < HDIM; d++) s = fmaf(Qs[w][d], Ks[m][d], s);
                s *= scale;
            }
            sc[r] = s; mx = fmaxf(mx, s);
        }
        for (int o = 16; o; o >>= 1) mx = fmaxf(mx, __shfl_xor_sync(~0u, mx, o));
        float sum = 0.f;
        #pragma unroll
        for (int r = 0; r < 4; r++){
            int m = lane + r*32;
            float e = (m < NTOK) ? expf(sc[r] - mx) : 0.f;
            sc[r] = e; sum += e;
        }
        for (int o = 16; o; o >>= 1) sum += __shfl_xor_sync(~0u, sum, o);
        float inv = 1.f / sum;
        #pragma unroll
        for (int r = 0; r < 4; r++){
            int m = lane + r*32;
            if (m < NTOK) Ps[w][m] = sc[r] * inv;
        }
        __syncwarp();
        for (int d = lane; d < HDIM; d += 32){
            float o = 0.f;
            for (int m = 0; m < NTOK; m++) o = fmaf(Ps[w][m], Vs[m][d], o);
            g_attnout[((size_t)b*NTOK + t)*CC + h*HDIM + d] = o;
        }
        __syncwarp();
    }
}

// ===================== transpose + bf16 split: [b][c][n] f32 -> [b][n][c] hi/lo ==========
__global__ void k_split_tr(const float* __restrict__ src,
                           __nv_bfloat16* __restrict__ dh, __nv_bfloat16* __restrict__ dl){
    __shared__ float t[32][33];
    int b = blockIdx.z;
    int n0 = blockIdx.x * 32, c0 = blockIdx.y * 32;
    const float* sp = src + (size_t)b * CC * NN;
    for (int r = threadIdx.y; r < 32; r += 8)
        t[r][threadIdx.x] = sp[(size_t)(c0 + r) * NN + n0 + threadIdx.x];
    __syncthreads();
    size_t ob = (size_t)b * NN * CC;
    for (int r = threadIdx.y; r < 32; r += 8){
        float v = t[threadIdx.x][r];
        __nv_bfloat16 h, l; split_bf16(v, h, l);
        size_t o = ob + (size_t)(n0 + r) * CC + c0 + threadIdx.x;
        dh[o] = h; dl[o] = l;
    }
}

// ===================== depthwise 3x3 + transpose + split fused =====================
__global__ void k_dwconv_t(const float* __restrict__ dw_w, const float* __restrict__ dw_b,
                           __nv_bfloat16* __restrict__ dh, __nv_bfloat16* __restrict__ dl){
    __shared__ float t[32][33];
    int b = blockIdx.z, c0 = blockIdx.y * 32, n0 = blockIdx.x * 32;
    for (int r = threadIdx.y; r < 32; r += 8){
        int c = c0 + r;
        int n = n0 + threadIdx.x;
        const float* src = g_h1 + ((size_t)b * CC + c) * NN;
        int y = n / WW, xp = n % WW;
        const float* w = dw_w + c * 9;
        float acc = dw_b[c];
        #pragma unroll
        for (int dy = -1; dy <= 1; dy++){
            int yy = y + dy;
            if (yy < 0 || yy >= HH) continue;
            #pragma unroll
            for (int dx = -1; dx <= 1; dx++){
                int xw = xp + dx;
                if (xw < 0 || xw >= WW) continue;
                acc = fmaf(src[yy*WW + xw], w[(dy+1)*3 + (dx+1)], acc);
            }
        }
        t[r][threadIdx.x] = acc;
    }
    __syncthreads();
    size_t ob = (size_t)b * NN * CC;
    for (int r = threadIdx.y; r < 32; r += 8){
        float v = t[threadIdx.x][r];
        __nv_bfloat16 h, l; split_bf16(v, h, l);
        size_t o = ob + (size_t)(n0 + r) * CC + c0 + threadIdx.x;
        dh[o] = h; dl[o] = l;
    }
}

// ===================== warp-mma bf16-split GEMM =====================
// C[m][n] = sum_k A[m][k] * B[n][k]   (A,B K-major bf16 hi/lo, fp32 accum, 3-product split)
// CTA tile 128x128, 8 warps (2m x 4n), warp tile 64x32, K = 384 in 12 chunks of 32.
// MODE 0: h1[b][m][n] = gelu(acc + bias[m])               (B has per-batch offset b*NN*CC)
// MODE 1: out[b][m][n] = acc + bias[m] + ptok_bg[b][m]
// MODE 2: qkv[m][n] = acc + bias[n]      (ld = 3*CC)
// MODE 3: ptok[m][n] = acc               (ld = CC)
#define LDS_B 80                      // smem row pitch bytes (32 bf16 + pad)
#define STG   (4*128*LDS_B)           // 40960 bytes per stage
#define MM_SMEM (2*STG)

template<int MODE>
__global__ void __launch_bounds__(256, 1)
k_mm(const __nv_bfloat16* __restrict__ Aph, const __nv_bfloat16* __restrict__ Apl,
     const __nv_bfloat16* __restrict__ Bh_, const __nv_bfloat16* __restrict__ Bl_,
     float* __restrict__ Out, const float* __restrict__ bias,
     int Mrows, int Nrows){
    extern __shared__ char smem[];
    uint32_t sb = smem_to_u32(smem);
    int tid = threadIdx.x, wid = tid >> 5, lane = tid & 31;
    int m0 = blockIdx.y * 128, n0 = blockIdx.x * 128;
    int b = blockIdx.z;
    const __nv_bfloat16* Bph = Bh_;
    const __nv_bfloat16* Bpl = Bl_;
    if (MODE <= 1){ Bph += (size_t)b * NN * CC; Bpl += (size_t)b * NN * CC; }

    #define LOADC(ch, st) do {                                                   \
        int k0 = (ch) * 32;                                                      \
        uint32_t s0 = sb + (st) * STG;                                           \
        for (int i = tid; i < 512; i += 256){                                    \
            int r = i >> 2, cu = i & 3;                                          \
            uint32_t dst = s0 + (uint32_t)(r * LDS_B + cu * 16);                 \
            int gm = m0 + r;                                                     \
            uint32_t szA = (gm < Mrows) ? 16u : 0u;                              \
            int gmc = gm < Mrows ? gm : 0;                                       \
            const char* pa = (const char*)(Aph + (size_t)gmc*CC + k0) + cu*16;   \
            const char* pal= (const char*)(Apl + (size_t)gmc*CC + k0) + cu*16;   \
            CP_ASYNC16(dst,         pa,  szA);                                   \
            CP_ASYNC16(dst + 10240, pal, szA);                                   \
            int gn = n0 + r;                                                     \
            uint32_t szB = (gn < Nrows) ? 16u : 0u;                              \
            int gnc = gn < Nrows ? gn : 0;                                       \
            const char* pb = (const char*)(Bph + (size_t)gnc*CC + k0) + cu*16;   \
            const char* pbl= (const char*)(Bpl + (size_t)gnc*CC + k0) + cu*16;   \
            CP_ASYNC16(dst + 20480, pb,  szB);                                   \
            CP_ASYNC16(dst + 30720, pbl, szB);                                   \
        }                                                                        \
        CP_ASYNC_COMMIT();                                                       \
    } while(0)

    float acc[4][4][4] = {};
    LOADC(0, 0);
    LOADC(1, 1);

    int wm = (wid >> 2) * 64, wn = (wid & 3) * 32;
    uint32_t a_row = (uint32_t)(wm + (lane & 15)) * LDS_B + ((lane >> 4) & 1) * 16;
    uint32_t b_row = (uint32_t)(wn + (lane & 7))  * LDS_B + ((lane >> 3) & 1) * 16;

    #pragma unroll 1
    for (int c = 0; c < 12; c++){
        CP_ASYNC_WAIT1();
        __syncthreads();
        uint32_t s0 = sb + (c & 1) * STG;
        #pragma unroll
        for (int kk = 0; kk < 2; kk++){
            uint32_t ah[4][4], al[4][4], bh[4][2], bl[4][2];
            #pragma unroll
            for (int i = 0; i < 4; i++){
                uint32_t ra = s0 + a_row + (uint32_t)(i * 16 * LDS_B) + kk * 32;
                ldsm_x4(ah[i], ra);
                ldsm_x4(al[i], ra + 10240);
            }
            #pragma unroll
            for (int j = 0; j < 4; j++){
                uint32_t rb = s0 + 20480 + b_row + (uint32_t)(j * 8 * LDS_B) + kk * 32;
                ldsm_x2(bh[j], rb);
                ldsm_x2(bl[j], rb + 10240);
            }
            #pragma unroll
            for (int i = 0; i < 4; i++)
                #pragma unroll
                for (int j = 0; j < 4; j++){
                    mma16816(acc[i][j], ah[i], bh[j]);
                    mma16816(acc[i][j], ah[i], bl[j]);
                    mma16816(acc[i][j], al[i], bh[j]);
                }
        }
        __syncthreads();
        if (c + 2 < 12) LOADC(c + 2, c & 1);
        else CP_ASYNC_COMMIT();
    }

    // ---- epilogue ----
    int mb = m0 + wm + (lane >> 2);
    int nb = n0 + wn + (lane & 3) * 2;
    #pragma unroll
    for (int i = 0; i < 4; i++){
        #pragma unroll
        for (int half = 0; half < 2; half++){
            int m = mb + i * 16 + half * 8;
            float bs = 0.f;
            if (MODE == 0) bs = bias[m];
            if (MODE == 1) bs = bias[m] + g_ptok[((size_t)b*NTOK + TOPK)*CC + m];
            #pragma unroll
            for (int j = 0; j < 4; j++){
                int n = nb + j * 8;
                float v0 = acc[i][j][half*2+0];
                float v1 = acc[i][j][half*2+1];
                if (MODE <= 1){
                    if (n >= Nrows) continue;
                    v0 += bs; v1 += bs;
                    if (MODE == 0){ v0 = gelu_exact(v0); v1 = gelu_exact(v1); }
                    float* p = Out + ((size_t)b*CC + m)*NN + n;
                    p[0] = v0; p[1] = v1;
                } else {
                    if (m >= Mrows) continue;
                    if (MODE == 2){ v0 += bias[n]; v1 += bias[n+1]; }
                    float* p = Out + (size_t)m * (MODE == 2 ? 3*CC : CC) + n;
                    p[0] = v0; p[1] = v1;
                }
            }
        }
    }
    #undef LOADC
}

// ===================== scatter projected top tokens =====================
__global__ void k_scatter(float* __restrict__ out){
    int b = blockIdx.x / TOPK, j = blockIdx.x % TOPK;
    int o = threadIdx.x;
    int n = g_topidx[b*TOPK + j];
    float d = g_ptok[((size_t)b*NTOK + j   )*CC + o]
            - g_ptok[((size_t)b*NTOK + TOPK)*CC + o];
    out[((size_t)b*CC + o)*NN + n] += d;
}

// ===================== host launch =====================
extern "C" void kernel_launch(void* const* d_in, const int* in_sizes, int n_in,
                              void* d_out, int out_size){
    const float* x      = (const float*)d_in[0];
    const float* qkv_w  = (const float*)d_in[1];
    const float* qkv_b  = (const float*)d_in[2];
    const float* proj_w = (const float*)d_in[3];
    const float* proj_b = (const float*)d_in[4];
    const float* bn_g   = (const float*)d_in[5];
    const float* bn_b   = (const float*)d_in[6];
    const float* fc1_w  = (const float*)d_in[7];
    const float* fc1_b  = (const float*)d_in[8];
    const float* fc2_w  = (const float*)d_in[9];
    const float* fc2_b  = (const float*)d_in[10];
    const float* dw_w   = (const float*)d_in[11];
    const float* dw_b   = (const float*)d_in[12];
    float* out = (float*)d_out;

    float *p_tokens, *p_qkv, *p_attnout, *p_ptok, *p_b1, *p_b2, *p_h1;
    __nv_bfloat16 *p_W1h, *p_W1l, *p_W2h, *p_W2l, *p_xth, *p_xtl;
    __nv_bfloat16 *p_tokh, *p_tokl, *p_aoh, *p_aol, *p_qwh, *p_qwl, *p_pwh, *p_pwl;
    cudaGetSymbolAddress((void**)&p_tokens , g_tokens);
    cudaGetSymbolAddress((void**)&p_qkv    , g_qkv);
    cudaGetSymbolAddress((void**)&p_attnout, g_attnout);
    cudaGetSymbolAddress((void**)&p_ptok   , g_ptok);
    cudaGetSymbolAddress((void**)&p_b1     , g_b1);
    cudaGetSymbolAddress((void**)&p_b2     , g_b2);
    cudaGetSymbolAddress((void**)&p_h1     , g_h1);
    cudaGetSymbolAddress((void**)&p_W1h    , g_W1h);
    cudaGetSymbolAddress((void**)&p_W1l    , g_W1l);
    cudaGetSymbolAddress((void**)&p_W2h    , g_W2h);
    cudaGetSymbolAddress((void**)&p_W2l    , g_W2l);
    cudaGetSymbolAddress((void**)&p_xth    , g_xth);
    cudaGetSymbolAddress((void**)&p_xtl    , g_xtl);
    cudaGetSymbolAddress((void**)&p_tokh   , g_tokh);
    cudaGetSymbolAddress((void**)&p_tokl   , g_tokl);
    cudaGetSymbolAddress((void**)&p_aoh    , g_aoh);
    cudaGetSymbolAddress((void**)&p_aol    , g_aol);
    cudaGetSymbolAddress((void**)&p_qwh    , g_qwh);
    cudaGetSymbolAddress((void**)&p_qwl    , g_qwl);
    cudaGetSymbolAddress((void**)&p_pwh    , g_pwh);
    cudaGetSymbolAddress((void**)&p_pwl    , g_pwl);

    cudaFuncSetAttribute(k_mm<0>, cudaFuncAttributeMaxDynamicSharedMemorySize, MM_SMEM);
    cudaFuncSetAttribute(k_mm<1>, cudaFuncAttributeMaxDynamicSharedMemorySize, MM_SMEM);
    cudaFuncSetAttribute(k_mm<2>, cudaFuncAttributeMaxDynamicSharedMemorySize, MM_SMEM);
    cudaFuncSetAttribute(k_mm<3>, cudaFuncAttributeMaxDynamicSharedMemorySize, MM_SMEM);

    // stats + weight prep
    k_colstats<<<BB*CC, 128>>>(x);
    k_scores  <<<dim3((NN + 255)/256, BB), 256>>>(x);
    k_bnstats <<<1, CC>>>(bn_g, bn_b);
    k_prepW1  <<<CC, CC>>>(fc1_w, fc1_b);
    k_prepW2  <<<CC, CC>>>(proj_w, fc2_w, fc2_b, proj_b);
    k_split_rows<<<(3*CC*CC + 255)/256, 256>>>(qkv_w,  p_qwh, p_qwl, 3*CC*CC);
    k_split_rows<<<(CC*CC   + 255)/256, 256>>>(proj_w, p_pwh, p_pwl, CC*CC);

    // x -> transposed bf16 split planes [b][n][c]
    k_split_tr<<<dim3(NN/32, CC/32, BB), dim3(32, 8)>>>(x, p_xth, p_xtl);

    // salience branch
    k_topk  <<<BB, 1024>>>();
    k_tokens<<<BB, CC>>>(x);
    k_split_rows<<<(MTOK*CC + 255)/256, 256>>>(p_tokens, p_tokh, p_tokl, MTOK*CC);
    k_mm<2><<<dim3(3*CC/128, (MTOK + 127)/128, 1), 256, MM_SMEM>>>(
        p_tokh, p_tokl, p_qwh, p_qwl, p_qkv, qkv_b, MTOK, 3*CC);
    k_attention<<<BB*NHEAD, 128>>>();
    k_split_rows<<<(MTOK*CC + 255)/256, 256>>>(p_attnout, p_aoh, p_aol, MTOK*CC);
    k_mm<3><<<dim3(CC/128, (MTOK + 127)/128, 1), 256, MM_SMEM>>>(
        p_aoh, p_aol, p_pwh, p_pwl, p_ptok, (const float*)nullptr, MTOK, CC);

    // conv-mixer branch on tensor cores (mma.sync)
    dim3 gbig((NN + 127)/128, CC/128, BB);
    k_mm<0><<<gbig, 256, MM_SMEM>>>(p_W1h, p_W1l, p_xth, p_xtl, p_h1, p_b1, CC, NN);
    k_dwconv_t<<<dim3(NN/32, CC/32, BB), dim3(32, 8)>>>(dw_w, dw_b, p_xth, p_xtl);
    k_mm<1><<<gbig, 256, MM_SMEM>>>(p_W2h, p_W2l, p_xth, p_xtl, out, p_b2, CC, NN);

    // rank-99 correction at top-token positions
    k_scatter<<<BB*TOPK, CC>>>(out);
}